// round 2
// baseline (speedup 1.0000x reference)
#include <cuda_runtime.h>
#include <cuda_bf16.h>
#include <stdint.h>

#define N_NODES_C 100000
#define N_EDGES_C 1600000
#define IN_DIM 32
#define HID_DIM 64
#define OUT_DIM 8

// ---------------- scratch (device globals; no allocation allowed) ----------
__device__ float g_deg [N_NODES_C];                 // in-degree (float)
__device__ float g_msg1[N_NODES_C * IN_DIM];        // sum_j x_j  per node
__device__ float g_msg2[N_NODES_C * OUT_DIM];       // sum_j p_j  per node
__device__ float g_p   [N_NODES_C * OUT_DIM];       // p = relu(h) @ W2_l^T
__device__ float g_r   [N_NODES_C * OUT_DIM];       // r = relu(h) @ W2_r^T
__device__ int   g_ei_is32;                         // 1 if edge_index is int32

// ---------------- vector reductions (sm_90+: red.global.add.v4.f32) --------
__device__ __forceinline__ void red_add_v4(float* addr, float4 v) {
    asm volatile("red.global.add.v4.f32 [%0], {%1, %2, %3, %4};"
                 :: "l"(addr), "f"(v.x), "f"(v.y), "f"(v.z), "f"(v.w)
                 : "memory");
}
__device__ __forceinline__ void red_add_f32(float* addr, float v) {
    asm volatile("red.global.add.f32 [%0], %1;"
                 :: "l"(addr), "f"(v) : "memory");
}

// edge fetch that works for both int32 and int64 edge_index layouts
__device__ __forceinline__ void load_edge(const void* ei, int e, int is32,
                                          int& src, int& dst) {
    if (is32) {
        const int* p = (const int*)ei;
        src = p[e];
        dst = p[N_EDGES_C + e];
    } else {
        const long long* p = (const long long*)ei;
        src = (int)p[e];
        dst = (int)p[N_EDGES_C + e];
    }
}

// ---------------- kernel 1: zero accumulators + detect edge dtype -----------
__global__ void k_zero(const void* __restrict__ ei) {
    const int stride = gridDim.x * blockDim.x;
    int t = blockIdx.x * blockDim.x + threadIdx.x;
    if (t == 0) {
        // If data is really int64 (values 0..99999), every int64 word is in
        // range. If it is int32, the packed high halves make huge values.
        const long long* p = (const long long*)ei;
        int is32 = 0;
        for (int i = 0; i < 128; ++i) {
            long long v = p[i];
            if (v < 0 || v >= (long long)N_NODES_C) { is32 = 1; break; }
        }
        g_ei_is32 = is32;
    }
    float4 z = make_float4(0.f, 0.f, 0.f, 0.f);
    float4* m1 = reinterpret_cast<float4*>(g_msg1);
    for (int i = t; i < N_NODES_C * IN_DIM / 4; i += stride) m1[i] = z;
    float4* m2 = reinterpret_cast<float4*>(g_msg2);
    for (int i = t; i < N_NODES_C * OUT_DIM / 4; i += stride) m2[i] = z;
    float4* dg = reinterpret_cast<float4*>(g_deg);
    for (int i = t; i < N_NODES_C / 4; i += stride) dg[i] = z;
}

// ---------------- kernel 2: scatter layer-1 messages + degree ---------------
// 8 threads per edge; each thread moves one float4 of x[src] into msg1[dst].
__global__ void __launch_bounds__(256) k_scatter1(const void* __restrict__ ei,
                                                  const float* __restrict__ x) {
    int t = blockIdx.x * blockDim.x + threadIdx.x;
    int e = t >> 3;
    int q = t & 7;
    if (e >= N_EDGES_C) return;
    int is32 = g_ei_is32;
    int src, dst;
    load_edge(ei, e, is32, src, dst);
    float4 v = *reinterpret_cast<const float4*>(x + (size_t)src * IN_DIM + q * 4);
    red_add_v4(g_msg1 + (size_t)dst * IN_DIM + q * 4, v);
    if (q == 0) red_add_f32(g_deg + dst, 1.0f);
}

// ---------------- kernel 3: fused layer1 + relu + both layer2 projections ---
// One warp per node. h (64 values) lives entirely in registers (2 per lane).
__global__ void __launch_bounds__(256) k_layer1(const float* __restrict__ x,
                                                const float* __restrict__ W1l,
                                                const float* __restrict__ b1,
                                                const float* __restrict__ W1r,
                                                const float* __restrict__ W2l,
                                                const float* __restrict__ W2r) {
    __shared__ float sW1lT[IN_DIM * HID_DIM];   // [f][o] transposed
    __shared__ float sW1rT[IN_DIM * HID_DIM];
    __shared__ float sW2l[OUT_DIM * HID_DIM];
    __shared__ float sW2r[OUT_DIM * HID_DIM];
    __shared__ float sb1[HID_DIM];

    int tid = threadIdx.x;
    for (int i = tid; i < HID_DIM * IN_DIM; i += 256) {
        int o = i / IN_DIM, f = i % IN_DIM;
        sW1lT[f * HID_DIM + o] = W1l[i];
        sW1rT[f * HID_DIM + o] = W1r[i];
    }
    for (int i = tid; i < OUT_DIM * HID_DIM; i += 256) {
        sW2l[i] = W2l[i];
        sW2r[i] = W2r[i];
    }
    if (tid < HID_DIM) sb1[tid] = b1[tid];
    __syncthreads();

    int warp = tid >> 5, lane = tid & 31;
    int node = blockIdx.x * 8 + warp;
    if (node >= N_NODES_C) return;

    float d   = g_deg[node];
    float inv = 1.0f / fmaxf(d, 1.0f);
    float xv  = x[(size_t)node * IN_DIM + lane];
    float av  = g_msg1[(size_t)node * IN_DIM + lane] * inv;

    float acc0 = sb1[lane];
    float acc1 = sb1[lane + 32];
#pragma unroll
    for (int f = 0; f < IN_DIM; ++f) {
        float xf = __shfl_sync(0xffffffffu, xv, f);
        float af = __shfl_sync(0xffffffffu, av, f);
        acc0 = fmaf(sW1lT[f * HID_DIM + lane],      af, acc0);
        acc0 = fmaf(sW1rT[f * HID_DIM + lane],      xf, acc0);
        acc1 = fmaf(sW1lT[f * HID_DIM + lane + 32], af, acc1);
        acc1 = fmaf(sW1rT[f * HID_DIM + lane + 32], xf, acc1);
    }
    float h0 = fmaxf(acc0, 0.0f);   // h[node][lane]
    float h1 = fmaxf(acc1, 0.0f);   // h[node][lane+32]

    float pc[OUT_DIM], rc[OUT_DIM];
#pragma unroll
    for (int c = 0; c < OUT_DIM; ++c) {
        pc[c] = fmaf(sW2l[c * HID_DIM + lane + 32], h1, sW2l[c * HID_DIM + lane] * h0);
        rc[c] = fmaf(sW2r[c * HID_DIM + lane + 32], h1, sW2r[c * HID_DIM + lane] * h0);
    }
#pragma unroll
    for (int off = 16; off > 0; off >>= 1) {
#pragma unroll
        for (int c = 0; c < OUT_DIM; ++c) {
            pc[c] += __shfl_xor_sync(0xffffffffu, pc[c], off);
            rc[c] += __shfl_xor_sync(0xffffffffu, rc[c], off);
        }
    }
    if (lane == 0) {
        float4* pp = reinterpret_cast<float4*>(g_p + (size_t)node * OUT_DIM);
        pp[0] = make_float4(pc[0], pc[1], pc[2], pc[3]);
        pp[1] = make_float4(pc[4], pc[5], pc[6], pc[7]);
        float4* rr = reinterpret_cast<float4*>(g_r + (size_t)node * OUT_DIM);
        rr[0] = make_float4(rc[0], rc[1], rc[2], rc[3]);
        rr[1] = make_float4(rc[4], rc[5], rc[6], rc[7]);
    }
}

// ---------------- kernel 4: scatter layer-2 (pre-projected, 8-d) ------------
// 2 threads per edge; each moves one float4 of p[src] into msg2[dst].
__global__ void __launch_bounds__(256) k_scatter2(const void* __restrict__ ei) {
    int t = blockIdx.x * blockDim.x + threadIdx.x;
    int e = t >> 1;
    int q = t & 1;
    if (e >= N_EDGES_C) return;
    int is32 = g_ei_is32;
    int src, dst;
    load_edge(ei, e, is32, src, dst);
    float4 v = *reinterpret_cast<const float4*>(g_p + (size_t)src * OUT_DIM + q * 4);
    red_add_v4(g_msg2 + (size_t)dst * OUT_DIM + q * 4, v);
}

// ---------------- kernel 5: finalize out = msg2/deg + b2 + r ----------------
__global__ void __launch_bounds__(256) k_final(const float* __restrict__ b2,
                                               float* __restrict__ out) {
    int i = blockIdx.x * blockDim.x + threadIdx.x;
    if (i >= N_NODES_C) return;
    float inv = 1.0f / fmaxf(g_deg[i], 1.0f);
    const float4* m = reinterpret_cast<const float4*>(g_msg2 + (size_t)i * OUT_DIM);
    const float4* r = reinterpret_cast<const float4*>(g_r + (size_t)i * OUT_DIM);
    float b2v[OUT_DIM];
#pragma unroll
    for (int c = 0; c < OUT_DIM; ++c) b2v[c] = b2[c];   // scalar: no alignment assumption
    float4 m0 = m[0], m1 = m[1];
    float4 r0 = r[0], r1 = r[1];
    float4 o0, o1;
    o0.x = fmaf(m0.x, inv, b2v[0]) + r0.x;
    o0.y = fmaf(m0.y, inv, b2v[1]) + r0.y;
    o0.z = fmaf(m0.z, inv, b2v[2]) + r0.z;
    o0.w = fmaf(m0.w, inv, b2v[3]) + r0.w;
    o1.x = fmaf(m1.x, inv, b2v[4]) + r1.x;
    o1.y = fmaf(m1.y, inv, b2v[5]) + r1.y;
    o1.z = fmaf(m1.z, inv, b2v[6]) + r1.z;
    o1.w = fmaf(m1.w, inv, b2v[7]) + r1.w;
    float4* op = reinterpret_cast<float4*>(out + (size_t)i * OUT_DIM);
    op[0] = o0;
    op[1] = o1;
}

// ---------------- launcher ---------------------------------------------------
extern "C" void kernel_launch(void* const* d_in, const int* in_sizes, int n_in,
                              void* d_out, int out_size) {
    // Map inputs robustly. Dict order: x, edge_index, W1_l, b1, W1_r, W2_l, b2, W2_r.
    // Alphabetical order: W1_l, W1_r, W2_l, W2_r, b1, b2, edge_index, x.
    int ix, iei, iW1l, ib1, iW1r, iW2l, ib2, iW2r;
    if (in_sizes[0] > 1000000) {        // dict order (x first)
        ix = 0; iei = 1; iW1l = 2; ib1 = 3; iW1r = 4; iW2l = 5; ib2 = 6; iW2r = 7;
    } else {                            // alphabetical
        iW1l = 0; iW1r = 1; iW2l = 2; iW2r = 3; ib1 = 4; ib2 = 5; iei = 6; ix = 7;
    }
    const float* x   = (const float*)d_in[ix];
    const void*  ei  = d_in[iei];                    // int32 or int64, detected on device
    const float* W1l = (const float*)d_in[iW1l];
    const float* b1  = (const float*)d_in[ib1];
    const float* W1r = (const float*)d_in[iW1r];
    const float* W2l = (const float*)d_in[iW2l];
    const float* b2  = (const float*)d_in[ib2];
    const float* W2r = (const float*)d_in[iW2r];
    float* out = (float*)d_out;

    k_zero<<<2048, 256>>>(ei);

    {   // scatter1: 8 threads per edge
        long long threads = (long long)N_EDGES_C * 8;
        int blocks = (int)((threads + 255) / 256);
        k_scatter1<<<blocks, 256>>>(ei, x);
    }
    {   // fused layer1 + projections: 1 warp per node, 8 nodes per block
        int blocks = (N_NODES_C + 7) / 8;
        k_layer1<<<blocks, 256>>>(x, W1l, b1, W1r, W2l, W2r);
    }
    {   // scatter2: 2 threads per edge
        long long threads = (long long)N_EDGES_C * 2;
        int blocks = (int)((threads + 255) / 256);
        k_scatter2<<<blocks, 256>>>(ei);
    }
    {   // finalize
        int blocks = (N_NODES_C + 255) / 256;
        k_final<<<blocks, 256>>>(b2, out);
    }
}

// round 3
// speedup vs baseline: 1.8161x; 1.8161x over previous
#include <cuda_runtime.h>
#include <cuda_bf16.h>
#include <stdint.h>

#define N_NODES_C 100000
#define N_EDGES_C 1600000
#define IN_DIM 32
#define HID_DIM 64
#define OUT_DIM 8
#define MAX_DEG 64

// ---------------- scratch (device globals; no allocation allowed) ----------
__device__ int   g_cnt[N_NODES_C];                  // in-degree (int)
__device__ int   g_csr[N_NODES_C * MAX_DEG];        // padded CSR: src lists per dst
__device__ float g_p  [N_NODES_C * OUT_DIM];        // p = relu(h) @ W2_l^T
__device__ float g_r  [N_NODES_C * OUT_DIM];        // r = relu(h) @ W2_r^T
__device__ int   g_ei_is32;                         // 1 if edge_index is int32

// ---------------- kernel 1: zero degree counters + detect edge dtype --------
__global__ void k_zero(const void* __restrict__ ei) {
    const int stride = gridDim.x * blockDim.x;
    int t = blockIdx.x * blockDim.x + threadIdx.x;
    if (t == 0) {
        // int64 edge values are all in [0, N). If the buffer is really int32,
        // interpreting pairs as int64 yields huge/negative values.
        const long long* p = (const long long*)ei;
        int is32 = 0;
        for (int i = 0; i < 128; ++i) {
            long long v = p[i];
            if (v < 0 || v >= (long long)N_NODES_C) { is32 = 1; break; }
        }
        g_ei_is32 = is32;
    }
    for (int i = t; i < N_NODES_C; i += stride) g_cnt[i] = 0;
}

// ---------------- kernel 2: build padded CSR (one int atomic per edge) ------
__global__ void __launch_bounds__(256) k_fill(const void* __restrict__ ei) {
    int e = blockIdx.x * blockDim.x + threadIdx.x;
    if (e >= N_EDGES_C) return;
    int src, dst;
    if (g_ei_is32) {
        const int* p = (const int*)ei;
        src = p[e];
        dst = p[N_EDGES_C + e];
    } else {
        const long long* p = (const long long*)ei;
        src = (int)p[e];
        dst = (int)p[N_EDGES_C + e];
    }
    int slot = atomicAdd(&g_cnt[dst], 1);
    if (slot < MAX_DEG) g_csr[dst * MAX_DEG + slot] = src;
}

// helper: broadcast csr entry j (0..63) from the two per-lane registers
__device__ __forceinline__ int bc_src(int s0, int s1, int j) {
    // j is warp-uniform here
    int v = (j < 32) ? s0 : s1;
    return __shfl_sync(0xffffffffu, v, j & 31);
}

// ---------------- kernel 3: gather-mean + layer1 + relu + W2 projections ----
// One warp per node, grid-stride. h (64 vals) lives in registers.
__global__ void __launch_bounds__(256) k_layerA(const float* __restrict__ x,
                                                const float* __restrict__ W1l,
                                                const float* __restrict__ b1,
                                                const float* __restrict__ W1r,
                                                const float* __restrict__ W2l,
                                                const float* __restrict__ W2r) {
    __shared__ float sW1lT[IN_DIM * HID_DIM];   // [f][o] transposed
    __shared__ float sW1rT[IN_DIM * HID_DIM];
    __shared__ float sW2l[OUT_DIM * HID_DIM];
    __shared__ float sW2r[OUT_DIM * HID_DIM];
    __shared__ float sb1[HID_DIM];

    int tid = threadIdx.x;
    for (int i = tid; i < HID_DIM * IN_DIM; i += 256) {
        int o = i / IN_DIM, f = i % IN_DIM;
        sW1lT[f * HID_DIM + o] = W1l[i];
        sW1rT[f * HID_DIM + o] = W1r[i];
    }
    for (int i = tid; i < OUT_DIM * HID_DIM; i += 256) {
        sW2l[i] = W2l[i];
        sW2r[i] = W2r[i];
    }
    if (tid < HID_DIM) sb1[tid] = b1[tid];
    __syncthreads();

    int warp = tid >> 5, lane = tid & 31;

    for (int node = blockIdx.x * 8 + warp; node < N_NODES_C; node += gridDim.x * 8) {
        int deg = min(g_cnt[node], MAX_DEG);
        const int* row = g_csr + node * MAX_DEG;
        int s0 = (lane      < deg) ? row[lane]      : 0;
        int s1 = (lane + 32 < deg) ? row[lane + 32] : 0;

        // gather-sum of neighbor features, 4-way MLP
        float a0 = 0.f, a1 = 0.f, a2 = 0.f, a3 = 0.f;
        int j = 0;
        for (; j + 4 <= deg; j += 4) {
            int sa = bc_src(s0, s1, j);
            int sb = bc_src(s0, s1, j + 1);
            int sc = bc_src(s0, s1, j + 2);
            int sd = bc_src(s0, s1, j + 3);
            a0 += x[sa * IN_DIM + lane];
            a1 += x[sb * IN_DIM + lane];
            a2 += x[sc * IN_DIM + lane];
            a3 += x[sd * IN_DIM + lane];
        }
        for (; j < deg; ++j) {
            int sa = bc_src(s0, s1, j);
            a0 += x[sa * IN_DIM + lane];
        }
        float inv = 1.0f / fmaxf((float)deg, 1.0f);
        float av  = ((a0 + a1) + (a2 + a3)) * inv;   // mean aggregation, this lane's feat
        float xv  = x[(size_t)node * IN_DIM + lane];

        float acc0 = sb1[lane];
        float acc1 = sb1[lane + 32];
#pragma unroll
        for (int f = 0; f < IN_DIM; ++f) {
            float xf = __shfl_sync(0xffffffffu, xv, f);
            float af = __shfl_sync(0xffffffffu, av, f);
            acc0 = fmaf(sW1lT[f * HID_DIM + lane],      af, acc0);
            acc0 = fmaf(sW1rT[f * HID_DIM + lane],      xf, acc0);
            acc1 = fmaf(sW1lT[f * HID_DIM + lane + 32], af, acc1);
            acc1 = fmaf(sW1rT[f * HID_DIM + lane + 32], xf, acc1);
        }
        float h0 = fmaxf(acc0, 0.0f);
        float h1 = fmaxf(acc1, 0.0f);

        float pc[OUT_DIM], rc[OUT_DIM];
#pragma unroll
        for (int c = 0; c < OUT_DIM; ++c) {
            pc[c] = fmaf(sW2l[c * HID_DIM + lane + 32], h1, sW2l[c * HID_DIM + lane] * h0);
            rc[c] = fmaf(sW2r[c * HID_DIM + lane + 32], h1, sW2r[c * HID_DIM + lane] * h0);
        }
#pragma unroll
        for (int off = 16; off > 0; off >>= 1) {
#pragma unroll
            for (int c = 0; c < OUT_DIM; ++c) {
                pc[c] += __shfl_xor_sync(0xffffffffu, pc[c], off);
                rc[c] += __shfl_xor_sync(0xffffffffu, rc[c], off);
            }
        }
        if (lane == 0) {
            float4* pp = reinterpret_cast<float4*>(g_p + (size_t)node * OUT_DIM);
            pp[0] = make_float4(pc[0], pc[1], pc[2], pc[3]);
            pp[1] = make_float4(pc[4], pc[5], pc[6], pc[7]);
            float4* rr = reinterpret_cast<float4*>(g_r + (size_t)node * OUT_DIM);
            rr[0] = make_float4(rc[0], rc[1], rc[2], rc[3]);
            rr[1] = make_float4(rc[4], rc[5], rc[6], rc[7]);
        }
    }
}

// ---------------- kernel 4: layer-2 gather-mean + finalize ------------------
// One warp per node: lanes = 8 features x 4 neighbor-groups.
__global__ void __launch_bounds__(256) k_layerB(const float* __restrict__ b2,
                                                float* __restrict__ out) {
    int tid = threadIdx.x, warp = tid >> 5, lane = tid & 31;
    int f = lane & 7, g = lane >> 3;   // g in 0..3

    for (int node = blockIdx.x * 8 + warp; node < N_NODES_C; node += gridDim.x * 8) {
        int deg = min(g_cnt[node], MAX_DEG);
        const int* row = g_csr + node * MAX_DEG;
        int s0 = (lane      < deg) ? row[lane]      : 0;
        int s1 = (lane + 32 < deg) ? row[lane + 32] : 0;

        float acc = 0.f;
        // first 32 neighbors
        int lim1 = min(deg, 32);
        int it1 = (lim1 + 3) >> 2;                 // warp-uniform trip count
        for (int it = 0; it < it1; ++it) {
            int j = it * 4 + g;                    // per-lane neighbor index
            int src = __shfl_sync(0xffffffffu, s0, j & 31);
            if (j < lim1) acc += g_p[src * OUT_DIM + f];
        }
        // neighbors 32..63
        int rem = deg - 32;
        int it2 = (rem > 0) ? ((rem + 3) >> 2) : 0;
        for (int it = 0; it < it2; ++it) {
            int j = it * 4 + g;
            int src = __shfl_sync(0xffffffffu, s1, j & 31);
            if (j < rem) acc += g_p[src * OUT_DIM + f];
        }
        // reduce over the 4 neighbor-groups
        acc += __shfl_xor_sync(0xffffffffu, acc, 8);
        acc += __shfl_xor_sync(0xffffffffu, acc, 16);

        if (g == 0) {
            float inv = 1.0f / fmaxf((float)deg, 1.0f);
            out[(size_t)node * OUT_DIM + f] =
                fmaf(acc, inv, b2[f]) + g_r[(size_t)node * OUT_DIM + f];
        }
    }
}

// ---------------- launcher ---------------------------------------------------
extern "C" void kernel_launch(void* const* d_in, const int* in_sizes, int n_in,
                              void* d_out, int out_size) {
    // Dict order: x, edge_index, W1_l, b1, W1_r, W2_l, b2, W2_r.
    // Alphabetical: W1_l, W1_r, W2_l, W2_r, b1, b2, edge_index, x.
    int ix, iei, iW1l, ib1, iW1r, iW2l, ib2, iW2r;
    if (in_sizes[0] > 1000000) {        // dict order (x first)
        ix = 0; iei = 1; iW1l = 2; ib1 = 3; iW1r = 4; iW2l = 5; ib2 = 6; iW2r = 7;
    } else {                            // alphabetical
        iW1l = 0; iW1r = 1; iW2l = 2; iW2r = 3; ib1 = 4; ib2 = 5; iei = 6; ix = 7;
    }
    const float* x   = (const float*)d_in[ix];
    const void*  ei  = d_in[iei];
    const float* W1l = (const float*)d_in[iW1l];
    const float* b1  = (const float*)d_in[ib1];
    const float* W1r = (const float*)d_in[iW1r];
    const float* W2l = (const float*)d_in[iW2l];
    const float* b2  = (const float*)d_in[ib2];
    const float* W2r = (const float*)d_in[iW2r];
    float* out = (float*)d_out;

    k_zero<<<512, 256>>>(ei);
    k_fill<<<(N_EDGES_C + 255) / 256, 256>>>(ei);
    k_layerA<<<1184, 256>>>(x, W1l, b1, W1r, W2l, W2r);
    k_layerB<<<1184, 256>>>(b2, out);
}

// round 4
// speedup vs baseline: 2.8346x; 1.5608x over previous
#include <cuda_runtime.h>
#include <cuda_bf16.h>
#include <stdint.h>

#define N_NODES_C 100000
#define N_EDGES_C 1600000
#define IN_DIM 32
#define HID_DIM 64
#define OUT_DIM 8
#define MAX_DEG 64
#define NPB 128              // nodes per k_gemm block

// ---------------- scratch (device globals; no allocation allowed) ----------
__device__ int   g_cnt[N_NODES_C];                  // in-degree
__device__ int   g_csr[N_NODES_C * MAX_DEG];        // padded CSR
__device__ float g_agg[N_NODES_C * IN_DIM];         // mean-aggregated x
__device__ float g_p  [N_NODES_C * OUT_DIM];        // relu(h) @ W2_l^T
__device__ float g_r  [N_NODES_C * OUT_DIM];        // relu(h) @ W2_r^T
__device__ int   g_ei_is32;

// ---------------- kernel 1: zero counters + detect edge dtype ---------------
__global__ void k_zero(const void* __restrict__ ei) {
    const int stride = gridDim.x * blockDim.x;
    int t = blockIdx.x * blockDim.x + threadIdx.x;
    if (t == 0) {
        const long long* p = (const long long*)ei;
        int is32 = 0;
        for (int i = 0; i < 128; ++i) {
            long long v = p[i];
            if (v < 0 || v >= (long long)N_NODES_C) { is32 = 1; break; }
        }
        g_ei_is32 = is32;
    }
    for (int i = t; i < N_NODES_C; i += stride) g_cnt[i] = 0;
}

// ---------------- kernel 2: build padded CSR --------------------------------
__global__ void __launch_bounds__(256) k_fill(const void* __restrict__ ei) {
    int e = blockIdx.x * blockDim.x + threadIdx.x;
    if (e >= N_EDGES_C) return;
    int src, dst;
    if (g_ei_is32) {
        const int* p = (const int*)ei;
        src = p[e];
        dst = p[N_EDGES_C + e];
    } else {
        const long long* p = (const long long*)ei;
        src = (int)p[e];
        dst = (int)p[N_EDGES_C + e];
    }
    int slot = atomicAdd(&g_cnt[dst], 1);
    if (slot < MAX_DEG) g_csr[dst * MAX_DEG + slot] = src;
}

__device__ __forceinline__ int bc_src(int s0, int s1, int j) {
    int v = (j < 32) ? s0 : s1;   // j warp-uniform
    return __shfl_sync(0xffffffffu, v, j & 31);
}

// ---------------- kernel 3: gather-mean of x into g_agg ---------------------
// One warp per node: lane = feature; each neighbor row is one 128B line.
__global__ void __launch_bounds__(256) k_agg(const float* __restrict__ x) {
    int tid = threadIdx.x, warp = tid >> 5, lane = tid & 31;
    int node = blockIdx.x * 8 + warp;
    if (node >= N_NODES_C) return;

    int deg = min(g_cnt[node], MAX_DEG);
    const int* row = g_csr + node * MAX_DEG;
    int s0 = (lane      < deg) ? row[lane]      : 0;
    int s1 = (lane + 32 < deg) ? row[lane + 32] : 0;

    float a0 = 0.f, a1 = 0.f, a2 = 0.f, a3 = 0.f;
    int j = 0;
    for (; j + 4 <= deg; j += 4) {
        int sa = bc_src(s0, s1, j);
        int sb = bc_src(s0, s1, j + 1);
        int sc = bc_src(s0, s1, j + 2);
        int sd = bc_src(s0, s1, j + 3);
        a0 += x[sa * IN_DIM + lane];
        a1 += x[sb * IN_DIM + lane];
        a2 += x[sc * IN_DIM + lane];
        a3 += x[sd * IN_DIM + lane];
    }
    for (; j < deg; ++j) a0 += x[bc_src(s0, s1, j) * IN_DIM + lane];

    float inv = 1.0f / fmaxf((float)deg, 1.0f);
    g_agg[(size_t)node * IN_DIM + lane] = ((a0 + a1) + (a2 + a3)) * inv;
}

// ---------------- kernel 4: block-tiled fused GEMM ---------------------------
// 128 nodes/block. h = relu([a|x] @ Wcat^T + b1); p = h@W2l^T; r = h@W2r^T.
// Thread tile: 8 outputs x 4 nodes (32 FMA per 3 LDS.128).
__global__ void __launch_bounds__(256) k_gemm(const float* __restrict__ x,
                                              const float* __restrict__ W1l,
                                              const float* __restrict__ b1,
                                              const float* __restrict__ W1r,
                                              const float* __restrict__ W2l,
                                              const float* __restrict__ W2r) {
    __shared__ float buf[64 * 132];        // phase1: sF[f][132]; phase2: sH[o][129]
    __shared__ float sWT[64 * 64];         // Wcat transposed [f][o]
    __shared__ float sW2[2 * 8 * HID_DIM]; // [m][c][o]
    __shared__ float sb1[HID_DIM];

    int t = threadIdx.x;
    int base = blockIdx.x * NPB;

    // ---- stage features f-major: sF[f][n], f<32 = a (mean agg), f>=32 = x ----
    for (int idx = t; idx < NPB * 8; idx += 256) {
        int n = idx >> 3, f4 = idx & 7;
        int node = base + n;
        float4 va = make_float4(0.f, 0.f, 0.f, 0.f);
        float4 vx = va;
        if (node < N_NODES_C) {
            va = *reinterpret_cast<const float4*>(g_agg + (size_t)node * IN_DIM + f4 * 4);
            vx = *reinterpret_cast<const float4*>(x     + (size_t)node * IN_DIM + f4 * 4);
        }
        int f = f4 * 4;
        buf[(f + 0) * 132 + n] = va.x;
        buf[(f + 1) * 132 + n] = va.y;
        buf[(f + 2) * 132 + n] = va.z;
        buf[(f + 3) * 132 + n] = va.w;
        buf[(f + 32) * 132 + n] = vx.x;
        buf[(f + 33) * 132 + n] = vx.y;
        buf[(f + 34) * 132 + n] = vx.z;
        buf[(f + 35) * 132 + n] = vx.w;
    }
    // ---- stage weights transposed ----
    for (int i = t; i < HID_DIM * IN_DIM; i += 256) {
        int f = i >> 6, o = i & 63;            // consecutive lanes -> consecutive o
        sWT[f * 64 + o]        = W1l[o * IN_DIM + f];
        sWT[(f + 32) * 64 + o] = W1r[o * IN_DIM + f];
    }
    for (int i = t; i < OUT_DIM * HID_DIM; i += 256) {
        sW2[i]                     = W2l[i];
        sW2[OUT_DIM * HID_DIM + i] = W2r[i];
    }
    if (t < HID_DIM) sb1[t] = b1[t];
    __syncthreads();

    // ---- main GEMM: warp og owns outputs og*8..og*8+7; lane nq owns nodes nq*4..+3
    int og = t >> 5, nq = t & 31;
    float acc[8][4];
#pragma unroll
    for (int ol = 0; ol < 8; ++ol) {
        float b = sb1[og * 8 + ol];
#pragma unroll
        for (int k = 0; k < 4; ++k) acc[ol][k] = b;
    }
#pragma unroll 4
    for (int f = 0; f < 64; ++f) {
        float4 v  = *reinterpret_cast<const float4*>(&buf[f * 132 + nq * 4]);
        float4 w0 = *reinterpret_cast<const float4*>(&sWT[f * 64 + og * 8]);
        float4 w1 = *reinterpret_cast<const float4*>(&sWT[f * 64 + og * 8 + 4]);
        acc[0][0] = fmaf(w0.x, v.x, acc[0][0]); acc[0][1] = fmaf(w0.x, v.y, acc[0][1]);
        acc[0][2] = fmaf(w0.x, v.z, acc[0][2]); acc[0][3] = fmaf(w0.x, v.w, acc[0][3]);
        acc[1][0] = fmaf(w0.y, v.x, acc[1][0]); acc[1][1] = fmaf(w0.y, v.y, acc[1][1]);
        acc[1][2] = fmaf(w0.y, v.z, acc[1][2]); acc[1][3] = fmaf(w0.y, v.w, acc[1][3]);
        acc[2][0] = fmaf(w0.z, v.x, acc[2][0]); acc[2][1] = fmaf(w0.z, v.y, acc[2][1]);
        acc[2][2] = fmaf(w0.z, v.z, acc[2][2]); acc[2][3] = fmaf(w0.z, v.w, acc[2][3]);
        acc[3][0] = fmaf(w0.w, v.x, acc[3][0]); acc[3][1] = fmaf(w0.w, v.y, acc[3][1]);
        acc[3][2] = fmaf(w0.w, v.z, acc[3][2]); acc[3][3] = fmaf(w0.w, v.w, acc[3][3]);
        acc[4][0] = fmaf(w1.x, v.x, acc[4][0]); acc[4][1] = fmaf(w1.x, v.y, acc[4][1]);
        acc[4][2] = fmaf(w1.x, v.z, acc[4][2]); acc[4][3] = fmaf(w1.x, v.w, acc[4][3]);
        acc[5][0] = fmaf(w1.y, v.x, acc[5][0]); acc[5][1] = fmaf(w1.y, v.y, acc[5][1]);
        acc[5][2] = fmaf(w1.y, v.z, acc[5][2]); acc[5][3] = fmaf(w1.y, v.w, acc[5][3]);
        acc[6][0] = fmaf(w1.z, v.x, acc[6][0]); acc[6][1] = fmaf(w1.z, v.y, acc[6][1]);
        acc[6][2] = fmaf(w1.z, v.z, acc[6][2]); acc[6][3] = fmaf(w1.z, v.w, acc[6][3]);
        acc[7][0] = fmaf(w1.w, v.x, acc[7][0]); acc[7][1] = fmaf(w1.w, v.y, acc[7][1]);
        acc[7][2] = fmaf(w1.w, v.z, acc[7][2]); acc[7][3] = fmaf(w1.w, v.w, acc[7][3]);
    }
    __syncthreads();   // done reading sF; reuse buf as sH[o][129]

#pragma unroll
    for (int ol = 0; ol < 8; ++ol) {
        int o = og * 8 + ol;
#pragma unroll
        for (int k = 0; k < 4; ++k)
            buf[o * 129 + nq * 4 + k] = fmaxf(acc[ol][k], 0.0f);
    }
    __syncthreads();

    // ---- projections: thread = (node n, matrix m) ----
    int n = t & 127, m = t >> 7;
    const float* W2 = sW2 + m * OUT_DIM * HID_DIM;
    float pa[8];
#pragma unroll
    for (int c = 0; c < 8; ++c) pa[c] = 0.f;
#pragma unroll 4
    for (int o = 0; o < HID_DIM; ++o) {
        float hv = buf[o * 129 + n];
#pragma unroll
        for (int c = 0; c < 8; ++c) pa[c] = fmaf(W2[c * HID_DIM + o], hv, pa[c]);
    }
    int node = base + n;
    if (node < N_NODES_C) {
        float* dst = (m == 0 ? g_p : g_r) + (size_t)node * OUT_DIM;
        reinterpret_cast<float4*>(dst)[0] = make_float4(pa[0], pa[1], pa[2], pa[3]);
        reinterpret_cast<float4*>(dst)[1] = make_float4(pa[4], pa[5], pa[6], pa[7]);
    }
}

// ---------------- kernel 5: layer-2 gather-mean + finalize (float4) ---------
// One warp per node: 2 lanes per neighbor, 16 neighbors per round.
__global__ void __launch_bounds__(256) k_layerB(const float* __restrict__ b2,
                                                float* __restrict__ out) {
    int tid = threadIdx.x, warp = tid >> 5, lane = tid & 31;
    int jl = lane >> 1, q = lane & 1;
    float4 b4 = *reinterpret_cast<const float4*>(b2 + q * 4);

    int node = blockIdx.x * 8 + warp;
    if (node >= N_NODES_C) return;

    int deg = min(g_cnt[node], MAX_DEG);
    const int* row = g_csr + node * MAX_DEG;
    int s0 = (lane      < deg) ? row[lane]      : 0;
    int s1 = (lane + 32 < deg) ? row[lane + 32] : 0;

    float4 acc = make_float4(0.f, 0.f, 0.f, 0.f);
    int rounds = (deg + 15) >> 4;
    for (int tr = 0; tr < rounds; ++tr) {
        int j = tr * 16 + jl;
        int s = (tr < 2) ? s0 : s1;
        int src = __shfl_sync(0xffffffffu, s, j & 31);
        if (j < deg) {
            float4 v = *reinterpret_cast<const float4*>(g_p + (size_t)src * OUT_DIM + q * 4);
            acc.x += v.x; acc.y += v.y; acc.z += v.z; acc.w += v.w;
        }
    }
#pragma unroll
    for (int off = 2; off <= 16; off <<= 1) {
        acc.x += __shfl_xor_sync(0xffffffffu, acc.x, off);
        acc.y += __shfl_xor_sync(0xffffffffu, acc.y, off);
        acc.z += __shfl_xor_sync(0xffffffffu, acc.z, off);
        acc.w += __shfl_xor_sync(0xffffffffu, acc.w, off);
    }
    if (lane < 2) {
        float inv = 1.0f / fmaxf((float)deg, 1.0f);
        float4 r = *reinterpret_cast<const float4*>(g_r + (size_t)node * OUT_DIM + q * 4);
        float4 o4;
        o4.x = fmaf(acc.x, inv, b4.x) + r.x;
        o4.y = fmaf(acc.y, inv, b4.y) + r.y;
        o4.z = fmaf(acc.z, inv, b4.z) + r.z;
        o4.w = fmaf(acc.w, inv, b4.w) + r.w;
        *reinterpret_cast<float4*>(out + (size_t)node * OUT_DIM + q * 4) = o4;
    }
}

// ---------------- launcher ---------------------------------------------------
extern "C" void kernel_launch(void* const* d_in, const int* in_sizes, int n_in,
                              void* d_out, int out_size) {
    int ix, iei, iW1l, ib1, iW1r, iW2l, ib2, iW2r;
    if (in_sizes[0] > 1000000) {        // dict order (x first)
        ix = 0; iei = 1; iW1l = 2; ib1 = 3; iW1r = 4; iW2l = 5; ib2 = 6; iW2r = 7;
    } else {                            // alphabetical
        iW1l = 0; iW1r = 1; iW2l = 2; iW2r = 3; ib1 = 4; ib2 = 5; iei = 6; ix = 7;
    }
    const float* x   = (const float*)d_in[ix];
    const void*  ei  = d_in[iei];
    const float* W1l = (const float*)d_in[iW1l];
    const float* b1  = (const float*)d_in[ib1];
    const float* W1r = (const float*)d_in[iW1r];
    const float* W2l = (const float*)d_in[iW2l];
    const float* b2  = (const float*)d_in[ib2];
    const float* W2r = (const float*)d_in[iW2r];
    float* out = (float*)d_out;

    k_zero<<<512, 256>>>(ei);
    k_fill<<<(N_EDGES_C + 255) / 256, 256>>>(ei);
    k_agg<<<(N_NODES_C + 7) / 8, 256>>>(x);
    k_gemm<<<(N_NODES_C + NPB - 1) / NPB, 256>>>(x, W1l, b1, W1r, W2l, W2r);
    k_layerB<<<(N_NODES_C + 7) / 8, 256>>>(b2, out);
}

// round 5
// speedup vs baseline: 2.9628x; 1.0452x over previous
#include <cuda_runtime.h>
#include <cuda_bf16.h>
#include <stdint.h>

#define N_NODES_C 100000
#define N_EDGES_C 1600000
#define IN_DIM 32
#define HID_DIM 64
#define OUT_DIM 8
#define MAX_DEG 64
#define NPB 128              // nodes per k_gemm block

typedef unsigned long long ull;

// ---------------- scratch (device globals; no allocation allowed) ----------
__device__ int   g_cnt[N_NODES_C];                  // in-degree
__device__ int   g_csr[N_NODES_C * MAX_DEG];        // padded CSR
__device__ float g_agg[N_NODES_C * IN_DIM];         // mean-aggregated x
__device__ float g_p  [N_NODES_C * OUT_DIM];        // relu(h) @ W2_l^T
__device__ float g_r  [N_NODES_C * OUT_DIM];        // relu(h) @ W2_r^T
__device__ int   g_ei_is32;

// ---------------- packed fp32x2 helpers (Blackwell FFMA2) -------------------
__device__ __forceinline__ ull ffma2(ull a, ull b, ull c) {
    ull d;
    asm("fma.rn.f32x2 %0, %1, %2, %3;" : "=l"(d) : "l"(a), "l"(b), "l"(c));
    return d;
}
__device__ __forceinline__ ull pack2(float lo, float hi) {
    ull d;
    asm("mov.b64 %0, {%1, %2};" : "=l"(d) : "f"(lo), "f"(hi));
    return d;
}
__device__ __forceinline__ void unpack2(ull v, float& lo, float& hi) {
    asm("mov.b64 {%0, %1}, %2;" : "=f"(lo), "=f"(hi) : "l"(v));
}

// ---------------- kernel 1: zero counters + detect edge dtype ---------------
__global__ void k_zero(const void* __restrict__ ei) {
    const int stride = gridDim.x * blockDim.x;
    int t = blockIdx.x * blockDim.x + threadIdx.x;
    if (t == 0) {
        const long long* p = (const long long*)ei;
        int is32 = 0;
        for (int i = 0; i < 128; ++i) {
            long long v = p[i];
            if (v < 0 || v >= (long long)N_NODES_C) { is32 = 1; break; }
        }
        g_ei_is32 = is32;
    }
    for (int i = t; i < N_NODES_C; i += stride) g_cnt[i] = 0;
}

// ---------------- kernel 2: build padded CSR --------------------------------
__global__ void __launch_bounds__(256) k_fill(const void* __restrict__ ei) {
    int e = blockIdx.x * blockDim.x + threadIdx.x;
    if (e >= N_EDGES_C) return;
    int src, dst;
    if (g_ei_is32) {
        const int* p = (const int*)ei;
        src = p[e];
        dst = p[N_EDGES_C + e];
    } else {
        const long long* p = (const long long*)ei;
        src = (int)p[e];
        dst = (int)p[N_EDGES_C + e];
    }
    int slot = atomicAdd(&g_cnt[dst], 1);
    if (slot < MAX_DEG) g_csr[dst * MAX_DEG + slot] = src;
}

// ---------------- kernel 3: gather-mean, 8 lanes per node -------------------
// Block = 256 threads = 32 nodes. Indices staged in smem; each LDG.128 serves
// 4 nodes in the warp concurrently (4 lines per warp-LDG).
__global__ void __launch_bounds__(256) k_agg(const float* __restrict__ x) {
    __shared__ int sIdx[32 * MAX_DEG];   // 8KB
    __shared__ int sDeg[32];

    int tid = threadIdx.x;
    int base = blockIdx.x * 32;          // 100000 = 32 * 3125, no partial block

    for (int i = tid; i < 32 * MAX_DEG; i += 256) {
        int nl = i >> 6;
        sIdx[i] = g_csr[(base + nl) * MAX_DEG + (i & 63)];
    }
    if (tid < 32) sDeg[tid] = min(g_cnt[base + tid], MAX_DEG);
    __syncthreads();

    int qid = tid >> 3;          // node within block
    int q   = tid & 7;           // feature quarter (4 floats)
    int deg = sDeg[qid];
    const int* row = &sIdx[qid * MAX_DEG];

    float4 a0 = make_float4(0.f, 0.f, 0.f, 0.f);
    float4 a1 = a0;
    int j = 0;
    for (; j + 2 <= deg; j += 2) {
        int sa = row[j], sb = row[j + 1];
        float4 va = *reinterpret_cast<const float4*>(x + (size_t)sa * IN_DIM + q * 4);
        float4 vb = *reinterpret_cast<const float4*>(x + (size_t)sb * IN_DIM + q * 4);
        a0.x += va.x; a0.y += va.y; a0.z += va.z; a0.w += va.w;
        a1.x += vb.x; a1.y += vb.y; a1.z += vb.z; a1.w += vb.w;
    }
    if (j < deg) {
        float4 va = *reinterpret_cast<const float4*>(x + (size_t)row[j] * IN_DIM + q * 4);
        a0.x += va.x; a0.y += va.y; a0.z += va.z; a0.w += va.w;
    }
    float inv = 1.0f / fmaxf((float)deg, 1.0f);
    float4 o4;
    o4.x = (a0.x + a1.x) * inv;
    o4.y = (a0.y + a1.y) * inv;
    o4.z = (a0.z + a1.z) * inv;
    o4.w = (a0.w + a1.w) * inv;
    *reinterpret_cast<float4*>(g_agg + (size_t)(base + qid) * IN_DIM + q * 4) = o4;
}

// ---------------- kernel 4: block-tiled fused GEMM (FFMA2) ------------------
// 128 nodes/block. h = relu([a|x] @ Wcat^T + b1); p = h@W2l^T; r = h@W2r^T.
// Accumulators are packed output-pairs {o,o+1}; features dup'd {a,a}.
__global__ void __launch_bounds__(256) k_gemm(const float* __restrict__ x,
                                              const float* __restrict__ W1l,
                                              const float* __restrict__ b1,
                                              const float* __restrict__ W1r,
                                              const float* __restrict__ W2l,
                                              const float* __restrict__ W2r) {
    __shared__ float buf[64 * 132];          // phase1: sF[f][132]; phase2: sH[o][129]
    __shared__ float sWT[64 * 64];           // Wcat transposed [f][o]
    __shared__ float sW2P[2 * HID_DIM * 8];  // [m][o][c] (c contiguous for pair loads)
    __shared__ float sb1[HID_DIM];

    int t = threadIdx.x;
    int base = blockIdx.x * NPB;

    // ---- stage features f-major: sF[f][n], f<32 = mean-agg, f>=32 = x ----
    for (int idx = t; idx < NPB * 8; idx += 256) {
        int n = idx >> 3, f4 = idx & 7;
        int node = base + n;
        float4 va = make_float4(0.f, 0.f, 0.f, 0.f);
        float4 vx = va;
        if (node < N_NODES_C) {
            va = *reinterpret_cast<const float4*>(g_agg + (size_t)node * IN_DIM + f4 * 4);
            vx = *reinterpret_cast<const float4*>(x     + (size_t)node * IN_DIM + f4 * 4);
        }
        int f = f4 * 4;
        buf[(f + 0) * 132 + n] = va.x;
        buf[(f + 1) * 132 + n] = va.y;
        buf[(f + 2) * 132 + n] = va.z;
        buf[(f + 3) * 132 + n] = va.w;
        buf[(f + 32) * 132 + n] = vx.x;
        buf[(f + 33) * 132 + n] = vx.y;
        buf[(f + 34) * 132 + n] = vx.z;
        buf[(f + 35) * 132 + n] = vx.w;
    }
    // ---- stage weights transposed ----
    for (int i = t; i < HID_DIM * IN_DIM; i += 256) {
        int f = i >> 6, o = i & 63;
        sWT[f * 64 + o]        = W1l[o * IN_DIM + f];
        sWT[(f + 32) * 64 + o] = W1r[o * IN_DIM + f];
    }
    // sW2P[m][o*8 + c] = W2m[c*64 + o]
    for (int i = t; i < 2 * HID_DIM * 8; i += 256) {
        int m = i >> 9, rem = i & 511, o = rem >> 3, c = rem & 7;
        sW2P[i] = (m == 0 ? W2l : W2r)[c * HID_DIM + o];
    }
    if (t < HID_DIM) sb1[t] = b1[t];
    __syncthreads();

    // ---- main GEMM: warp og owns outputs og*8..+7 (as 4 pairs); lane nq owns 4 nodes
    int og = t >> 5, nq = t & 31;
    ull acc[4][4];   // [node k][output-pair op]
    {
        const ull* bp = reinterpret_cast<const ull*>(&sb1[og * 8]);
        ull b0 = bp[0], b1p = bp[1], b2 = bp[2], b3 = bp[3];
#pragma unroll
        for (int k = 0; k < 4; ++k) {
            acc[k][0] = b0; acc[k][1] = b1p; acc[k][2] = b2; acc[k][3] = b3;
        }
    }
#pragma unroll 4
    for (int f = 0; f < 64; ++f) {
        float4 v = *reinterpret_cast<const float4*>(&buf[f * 132 + nq * 4]);
        const ulonglong2* wp = reinterpret_cast<const ulonglong2*>(&sWT[f * 64 + og * 8]);
        ulonglong2 wa = wp[0];   // {w0,w1},{w2,w3}
        ulonglong2 wb = wp[1];   // {w4,w5},{w6,w7}
        ull a0 = pack2(v.x, v.x);
        ull a1 = pack2(v.y, v.y);
        ull a2 = pack2(v.z, v.z);
        ull a3 = pack2(v.w, v.w);
        acc[0][0] = ffma2(wa.x, a0, acc[0][0]); acc[0][1] = ffma2(wa.y, a0, acc[0][1]);
        acc[0][2] = ffma2(wb.x, a0, acc[0][2]); acc[0][3] = ffma2(wb.y, a0, acc[0][3]);
        acc[1][0] = ffma2(wa.x, a1, acc[1][0]); acc[1][1] = ffma2(wa.y, a1, acc[1][1]);
        acc[1][2] = ffma2(wb.x, a1, acc[1][2]); acc[1][3] = ffma2(wb.y, a1, acc[1][3]);
        acc[2][0] = ffma2(wa.x, a2, acc[2][0]); acc[2][1] = ffma2(wa.y, a2, acc[2][1]);
        acc[2][2] = ffma2(wb.x, a2, acc[2][2]); acc[2][3] = ffma2(wb.y, a2, acc[2][3]);
        acc[3][0] = ffma2(wa.x, a3, acc[3][0]); acc[3][1] = ffma2(wa.y, a3, acc[3][1]);
        acc[3][2] = ffma2(wb.x, a3, acc[3][2]); acc[3][3] = ffma2(wb.y, a3, acc[3][3]);
    }
    __syncthreads();   // done reading sF; reuse buf as sH[o][129]

#pragma unroll
    for (int op = 0; op < 4; ++op) {
        int o = og * 8 + op * 2;
#pragma unroll
        for (int k = 0; k < 4; ++k) {
            float lo, hi;
            unpack2(acc[k][op], lo, hi);
            buf[o * 129 + nq * 4 + k]       = fmaxf(lo, 0.0f);
            buf[(o + 1) * 129 + nq * 4 + k] = fmaxf(hi, 0.0f);
        }
    }
    __syncthreads();

    // ---- projections (FFMA2): thread = (node n, matrix m); 8 outputs as 4 pairs
    int n = t & 127, m = t >> 7;
    const float* W2 = sW2P + m * HID_DIM * 8;
    ull pa[4];
#pragma unroll
    for (int c = 0; c < 4; ++c) pa[c] = 0ull;
#pragma unroll 4
    for (int o = 0; o < HID_DIM; ++o) {
        float hv = buf[o * 129 + n];
        ull h2 = pack2(hv, hv);
        const ulonglong2* wp = reinterpret_cast<const ulonglong2*>(&W2[o * 8]);
        ulonglong2 wa = wp[0], wb = wp[1];
        pa[0] = ffma2(wa.x, h2, pa[0]);
        pa[1] = ffma2(wa.y, h2, pa[1]);
        pa[2] = ffma2(wb.x, h2, pa[2]);
        pa[3] = ffma2(wb.y, h2, pa[3]);
    }
    int node = base + n;
    if (node < N_NODES_C) {
        float o0, o1, o2, o3, o4, o5, o6, o7;
        unpack2(pa[0], o0, o1); unpack2(pa[1], o2, o3);
        unpack2(pa[2], o4, o5); unpack2(pa[3], o6, o7);
        float* dst = (m == 0 ? g_p : g_r) + (size_t)node * OUT_DIM;
        reinterpret_cast<float4*>(dst)[0] = make_float4(o0, o1, o2, o3);
        reinterpret_cast<float4*>(dst)[1] = make_float4(o4, o5, o6, o7);
    }
}

// ---------------- kernel 5: layer-2 gather-mean + finalize (float4) ---------
__global__ void __launch_bounds__(256) k_layerB(const float* __restrict__ b2,
                                                float* __restrict__ out) {
    int tid = threadIdx.x, warp = tid >> 5, lane = tid & 31;
    int jl = lane >> 1, q = lane & 1;
    float4 b4 = *reinterpret_cast<const float4*>(b2 + q * 4);

    int node = blockIdx.x * 8 + warp;
    if (node >= N_NODES_C) return;

    int deg = min(g_cnt[node], MAX_DEG);
    const int* row = g_csr + node * MAX_DEG;
    int s0 = (lane      < deg) ? row[lane]      : 0;
    int s1 = (lane + 32 < deg) ? row[lane + 32] : 0;

    float4 acc = make_float4(0.f, 0.f, 0.f, 0.f);
    int rounds = (deg + 15) >> 4;
    for (int tr = 0; tr < rounds; ++tr) {
        int j = tr * 16 + jl;
        int s = (tr < 2) ? s0 : s1;
        int src = __shfl_sync(0xffffffffu, s, j & 31);
        if (j < deg) {
            float4 v = *reinterpret_cast<const float4*>(g_p + (size_t)src * OUT_DIM + q * 4);
            acc.x += v.x; acc.y += v.y; acc.z += v.z; acc.w += v.w;
        }
    }
#pragma unroll
    for (int off = 2; off <= 16; off <<= 1) {
        acc.x += __shfl_xor_sync(0xffffffffu, acc.x, off);
        acc.y += __shfl_xor_sync(0xffffffffu, acc.y, off);
        acc.z += __shfl_xor_sync(0xffffffffu, acc.z, off);
        acc.w += __shfl_xor_sync(0xffffffffu, acc.w, off);
    }
    if (lane < 2) {
        float inv = 1.0f / fmaxf((float)deg, 1.0f);
        float4 r = *reinterpret_cast<const float4*>(g_r + (size_t)node * OUT_DIM + q * 4);
        float4 o4;
        o4.x = fmaf(acc.x, inv, b4.x) + r.x;
        o4.y = fmaf(acc.y, inv, b4.y) + r.y;
        o4.z = fmaf(acc.z, inv, b4.z) + r.z;
        o4.w = fmaf(acc.w, inv, b4.w) + r.w;
        *reinterpret_cast<float4*>(out + (size_t)node * OUT_DIM + q * 4) = o4;
    }
}

// ---------------- launcher ---------------------------------------------------
extern "C" void kernel_launch(void* const* d_in, const int* in_sizes, int n_in,
                              void* d_out, int out_size) {
    int ix, iei, iW1l, ib1, iW1r, iW2l, ib2, iW2r;
    if (in_sizes[0] > 1000000) {        // dict order (x first)
        ix = 0; iei = 1; iW1l = 2; ib1 = 3; iW1r = 4; iW2l = 5; ib2 = 6; iW2r = 7;
    } else {                            // alphabetical
        iW1l = 0; iW1r = 1; iW2l = 2; iW2r = 3; ib1 = 4; ib2 = 5; iei = 6; ix = 7;
    }
    const float* x   = (const float*)d_in[ix];
    const void*  ei  = d_in[iei];
    const float* W1l = (const float*)d_in[iW1l];
    const float* b1  = (const float*)d_in[ib1];
    const float* W1r = (const float*)d_in[iW1r];
    const float* W2l = (const float*)d_in[iW2l];
    const float* b2  = (const float*)d_in[ib2];
    const float* W2r = (const float*)d_in[iW2r];
    float* out = (float*)d_out;

    k_zero<<<512, 256>>>(ei);
    k_fill<<<(N_EDGES_C + 255) / 256, 256>>>(ei);
    k_agg<<<N_NODES_C / 32, 256>>>(x);
    k_gemm<<<(N_NODES_C + NPB - 1) / NPB, 256>>>(x, W1l, b1, W1r, W2l, W2r);
    k_layerB<<<(N_NODES_C + 7) / 8, 256>>>(b2, out);
}

// round 7
// speedup vs baseline: 3.4440x; 1.1624x over previous
#include <cuda_runtime.h>
#include <cuda_bf16.h>
#include <stdint.h>

#define N_NODES_C 100000
#define N_EDGES_C 1600000
#define IN_DIM 32
#define HID_DIM 64
#define OUT_DIM 8
#define MAX_DEG 64
#define NPB 128              // nodes per k_gemm block (MMA M)

typedef unsigned long long ull;

// ---------------- scratch (device globals; no allocation allowed) ----------
__device__ int   g_cnt[N_NODES_C];
__device__ int   g_csr[N_NODES_C * MAX_DEG];
__device__ float g_agg[N_NODES_C * IN_DIM];
__device__ float g_p  [N_NODES_C * OUT_DIM];
__device__ float g_r  [N_NODES_C * OUT_DIM];
__device__ int   g_ei_is32;

// ---------------- packed fp32x2 helpers --------------------------------------
__device__ __forceinline__ ull ffma2(ull a, ull b, ull c) {
    ull d;
    asm("fma.rn.f32x2 %0, %1, %2, %3;" : "=l"(d) : "l"(a), "l"(b), "l"(c));
    return d;
}
__device__ __forceinline__ ull pack2(float lo, float hi) {
    ull d;
    asm("mov.b64 %0, {%1, %2};" : "=l"(d) : "f"(lo), "f"(hi));
    return d;
}
__device__ __forceinline__ void unpack2(ull v, float& lo, float& hi) {
    asm("mov.b64 {%0, %1}, %2;" : "=f"(lo), "=f"(hi) : "l"(v));
}

// ---------------- warp-MMA helpers (sm_80+ PTX, legal on compute_103) --------
__device__ __forceinline__ uint32_t smem_u32(const void* p) {
    uint32_t a;
    asm("{ .reg .u64 t; cvta.to.shared.u64 t, %1; cvt.u32.u64 %0, t; }"
        : "=r"(a) : "l"(p));
    return a;
}
__device__ __forceinline__ void ldsm_x4(uint32_t addr, uint32_t& r0, uint32_t& r1,
                                        uint32_t& r2, uint32_t& r3) {
    asm volatile("ldmatrix.sync.aligned.m8n8.x4.shared.b16 {%0,%1,%2,%3}, [%4];"
                 : "=r"(r0), "=r"(r1), "=r"(r2), "=r"(r3) : "r"(addr));
}
__device__ __forceinline__ void mma_bf16(float* c, const uint32_t* a,
                                         uint32_t b0, uint32_t b1) {
    asm volatile("mma.sync.aligned.m16n8k16.row.col.f32.bf16.bf16.f32 "
                 "{%0,%1,%2,%3}, {%4,%5,%6,%7}, {%8,%9}, {%0,%1,%2,%3};"
                 : "+f"(c[0]), "+f"(c[1]), "+f"(c[2]), "+f"(c[3])
                 : "r"(a[0]), "r"(a[1]), "r"(a[2]), "r"(a[3]), "r"(b0), "r"(b1));
}
__device__ __forceinline__ void f2bf_hilo(float v, unsigned short& h, unsigned short& l) {
    __nv_bfloat16 hb = __float2bfloat16_rn(v);
    float r = v - __bfloat162float(hb);
    __nv_bfloat16 lb = __float2bfloat16_rn(r);
    h = __bfloat16_as_ushort(hb);
    l = __bfloat16_as_ushort(lb);
}

// smem layout for k_gemm (dynamic): strides in bf16 elements
#define STRA 136                         // 128 data + 8 pad  (272B rows)
#define OFF_A 0                          // A: 128 rows -> 34816 B
#define OFF_B 34816                      // B: 64 rows  -> 17408 B
#define OFF_W2 52224                     // 2*64*8 floats = 4096 B
#define OFF_B1 56320                     // 64 floats = 256 B
#define SMEM_GEMM 56576

// ---------------- kernel 1: zero counters + detect edge dtype ---------------
__global__ void k_zero(const void* __restrict__ ei) {
    const int stride = gridDim.x * blockDim.x;
    int t = blockIdx.x * blockDim.x + threadIdx.x;
    if (t == 0) {
        const long long* p = (const long long*)ei;
        int is32 = 0;
        for (int i = 0; i < 128; ++i) {
            long long v = p[i];
            if (v < 0 || v >= (long long)N_NODES_C) { is32 = 1; break; }
        }
        g_ei_is32 = is32;
    }
    for (int i = t; i < N_NODES_C; i += stride) g_cnt[i] = 0;
}

// ---------------- kernel 2: build padded CSR --------------------------------
__global__ void __launch_bounds__(256) k_fill(const void* __restrict__ ei) {
    int e = blockIdx.x * blockDim.x + threadIdx.x;
    if (e >= N_EDGES_C) return;
    int src, dst;
    if (g_ei_is32) {
        const int* p = (const int*)ei;
        src = p[e];
        dst = p[N_EDGES_C + e];
    } else {
        const long long* p = (const long long*)ei;
        src = (int)p[e];
        dst = (int)p[N_EDGES_C + e];
    }
    int slot = atomicAdd(&g_cnt[dst], 1);
    if (slot < MAX_DEG) g_csr[dst * MAX_DEG + slot] = src;
}

// ---------------- kernel 3: gather-mean, 8 lanes per node -------------------
__global__ void __launch_bounds__(256) k_agg(const float* __restrict__ x) {
    __shared__ int sIdx[32 * MAX_DEG];
    __shared__ int sDeg[32];

    int tid = threadIdx.x;
    int base = blockIdx.x * 32;

    for (int i = tid; i < 32 * MAX_DEG; i += 256) {
        int nl = i >> 6;
        sIdx[i] = g_csr[(base + nl) * MAX_DEG + (i & 63)];
    }
    if (tid < 32) sDeg[tid] = min(g_cnt[base + tid], MAX_DEG);
    __syncthreads();

    int qid = tid >> 3, q = tid & 7;
    int deg = sDeg[qid];
    const int* row = &sIdx[qid * MAX_DEG];

    float4 a0 = make_float4(0.f, 0.f, 0.f, 0.f);
    float4 a1 = a0;
    int j = 0;
    for (; j + 2 <= deg; j += 2) {
        int sa = row[j], sb = row[j + 1];
        float4 va = *reinterpret_cast<const float4*>(x + (size_t)sa * IN_DIM + q * 4);
        float4 vb = *reinterpret_cast<const float4*>(x + (size_t)sb * IN_DIM + q * 4);
        a0.x += va.x; a0.y += va.y; a0.z += va.z; a0.w += va.w;
        a1.x += vb.x; a1.y += vb.y; a1.z += vb.z; a1.w += vb.w;
    }
    if (j < deg) {
        float4 va = *reinterpret_cast<const float4*>(x + (size_t)row[j] * IN_DIM + q * 4);
        a0.x += va.x; a0.y += va.y; a0.z += va.z; a0.w += va.w;
    }
    float inv = 1.0f / fmaxf((float)deg, 1.0f);
    float4 o4;
    o4.x = (a0.x + a1.x) * inv;
    o4.y = (a0.y + a1.y) * inv;
    o4.z = (a0.z + a1.z) * inv;
    o4.w = (a0.w + a1.w) * inv;
    *reinterpret_cast<float4*>(g_agg + (size_t)(base + qid) * IN_DIM + q * 4) = o4;
}

// ---------------- kernel 4: HMMA fused GEMM (bf16 hi/lo) --------------------
// D[128x64] = F[128x64] @ Wcat^T via mma.sync m16n8k16; 12 K-steps cover
// hi*hi + lo*hi + hi*lo. Then relu+bias -> h smem -> f32x2 projections.
__global__ void __launch_bounds__(256) k_gemm(const float* __restrict__ x,
                                              const float* __restrict__ W1l,
                                              const float* __restrict__ b1,
                                              const float* __restrict__ W1r,
                                              const float* __restrict__ W2l,
                                              const float* __restrict__ W2r) {
    extern __shared__ unsigned char dynsmem[];
    unsigned short* sA = reinterpret_cast<unsigned short*>(dynsmem + OFF_A);
    unsigned short* sB = reinterpret_cast<unsigned short*>(dynsmem + OFF_B);
    float* sW2P = reinterpret_cast<float*>(dynsmem + OFF_W2);
    float* sb1  = reinterpret_cast<float*>(dynsmem + OFF_B1);
    float* hbuf = reinterpret_cast<float*>(dynsmem + OFF_A);   // reused post-MMA

    const uint32_t sA_u = smem_u32(sA);
    const uint32_t sB_u = smem_u32(sB);

    int t = threadIdx.x;
    int wid = t >> 5, lane = t & 31;
    int base = blockIdx.x * NPB;

    // ---- stage A rows: [hi(64) | lo(64)] bf16, feats = (agg | x) ----
    for (int idx = t; idx < NPB * 16; idx += 256) {
        int n = idx >> 4, f4 = idx & 15;
        int node = base + n;
        float4 v = make_float4(0.f, 0.f, 0.f, 0.f);
        if (node < N_NODES_C) {
            v = (f4 < 8)
                ? *reinterpret_cast<const float4*>(g_agg + (size_t)node * IN_DIM + f4 * 4)
                : *reinterpret_cast<const float4*>(x + (size_t)node * IN_DIM + (f4 - 8) * 4);
        }
        float vv[4] = {v.x, v.y, v.z, v.w};
        unsigned short hs[4], ls[4];
#pragma unroll
        for (int k = 0; k < 4; ++k) f2bf_hilo(vv[k], hs[k], ls[k]);
        uint2 hu, lu;
        hu.x = (uint32_t)hs[0] | ((uint32_t)hs[1] << 16);
        hu.y = (uint32_t)hs[2] | ((uint32_t)hs[3] << 16);
        lu.x = (uint32_t)ls[0] | ((uint32_t)ls[1] << 16);
        lu.y = (uint32_t)ls[2] | ((uint32_t)ls[3] << 16);
        *reinterpret_cast<uint2*>(sA + n * STRA + f4 * 4)      = hu;
        *reinterpret_cast<uint2*>(sA + n * STRA + 64 + f4 * 4) = lu;
    }
    // ---- stage B rows (Wcat [o][f]): [hi(64) | lo(64)] ----
    for (int idx = t; idx < 64 * 16; idx += 256) {
        int o = idx >> 4, f4 = idx & 15;
        float4 v = (f4 < 8)
            ? *reinterpret_cast<const float4*>(W1l + o * IN_DIM + f4 * 4)
            : *reinterpret_cast<const float4*>(W1r + o * IN_DIM + (f4 - 8) * 4);
        float vv[4] = {v.x, v.y, v.z, v.w};
        unsigned short hs[4], ls[4];
#pragma unroll
        for (int k = 0; k < 4; ++k) f2bf_hilo(vv[k], hs[k], ls[k]);
        uint2 hu, lu;
        hu.x = (uint32_t)hs[0] | ((uint32_t)hs[1] << 16);
        hu.y = (uint32_t)hs[2] | ((uint32_t)hs[3] << 16);
        lu.x = (uint32_t)ls[0] | ((uint32_t)ls[1] << 16);
        lu.y = (uint32_t)ls[2] | ((uint32_t)ls[3] << 16);
        *reinterpret_cast<uint2*>(sB + o * STRA + f4 * 4)      = hu;
        *reinterpret_cast<uint2*>(sB + o * STRA + 64 + f4 * 4) = lu;
    }
    // ---- stage projection weights + bias ----
    for (int i = t; i < 2 * HID_DIM * 8; i += 256) {
        int m = i >> 9, rem = i & 511, o = rem >> 3, c = rem & 7;
        sW2P[i] = (m == 0 ? W2l : W2r)[c * HID_DIM + o];
    }
    if (t < HID_DIM) sb1[t] = b1[t];
    __syncthreads();

    // ---- warp MMA: warp wid owns rows wid*16..+15; C[8 ntiles][4] fp32 ----
    float c[8][4];
#pragma unroll
    for (int nt = 0; nt < 8; ++nt)
#pragma unroll
        for (int k = 0; k < 4; ++k) c[nt][k] = 0.f;

    // A fragment address (per lane): row = wid*16 + (lane&15), col = ka*16 + (lane>>4)*8
    const uint32_t a_base = sA_u + (uint32_t)(((wid * 16 + (lane & 15)) * STRA + (lane >> 4) * 8) * 2);
    // B fragment address: q=lane>>3, rr=lane&7 -> n = n0 + (q>>1)*8 + rr, col = kb*16 + (q&1)*8
    const int q = lane >> 3, rr = lane & 7;
    const uint32_t b_base = sB_u + (uint32_t)((((q >> 1) * 8 + rr) * STRA + (q & 1) * 8) * 2);

    const int ka_tab[12] = {0, 1, 2, 3, 4, 5, 6, 7, 0, 1, 2, 3};   // A: hi,lo,hi
    const int kb_tab[12] = {0, 1, 2, 3, 0, 1, 2, 3, 4, 5, 6, 7};   // B: hi,hi,lo
#pragma unroll
    for (int s = 0; s < 12; ++s) {
        uint32_t a[4];
        ldsm_x4(a_base + (uint32_t)(ka_tab[s] * 32), a[0], a[1], a[2], a[3]);
        uint32_t koff = (uint32_t)(kb_tab[s] * 32);
#pragma unroll
        for (int np = 0; np < 4; ++np) {       // n-pair: ntiles 2np, 2np+1
            uint32_t b0, b1v, b2, b3;
            ldsm_x4(b_base + (uint32_t)(np * 16 * STRA * 2) + koff, b0, b1v, b2, b3);
            mma_bf16(c[2 * np],     a, b0, b1v);
            mma_bf16(c[2 * np + 1], a, b2, b3);
        }
    }
    __syncthreads();   // everyone done reading sA/sB; hbuf aliases sA

    // ---- epilogue: relu+bias -> hbuf[o*132 + n] ----
    {
        int g = lane >> 2, cc = lane & 3;
        int m0 = wid * 16 + g;
#pragma unroll
        for (int nt = 0; nt < 8; ++nt) {
            int o0 = nt * 8 + 2 * cc;
            float bi0 = sb1[o0], bi1 = sb1[o0 + 1];
            hbuf[o0 * 132 + m0]           = fmaxf(c[nt][0] + bi0, 0.f);
            hbuf[(o0 + 1) * 132 + m0]     = fmaxf(c[nt][1] + bi1, 0.f);
            hbuf[o0 * 132 + m0 + 8]       = fmaxf(c[nt][2] + bi0, 0.f);
            hbuf[(o0 + 1) * 132 + m0 + 8] = fmaxf(c[nt][3] + bi1, 0.f);
        }
    }
    __syncthreads();

    // ---- projections (f32x2): thread = (node n, matrix m) ----
    int n = t & 127, m = t >> 7;
    const float* W2 = sW2P + m * HID_DIM * 8;
    ull pa[4];
#pragma unroll
    for (int cc = 0; cc < 4; ++cc) pa[cc] = 0ull;
#pragma unroll 4
    for (int o = 0; o < HID_DIM; ++o) {
        float hv = hbuf[o * 132 + n];
        ull h2 = pack2(hv, hv);
        const ulonglong2* wp = reinterpret_cast<const ulonglong2*>(&W2[o * 8]);
        ulonglong2 wa = wp[0], wb = wp[1];
        pa[0] = ffma2(wa.x, h2, pa[0]);
        pa[1] = ffma2(wa.y, h2, pa[1]);
        pa[2] = ffma2(wb.x, h2, pa[2]);
        pa[3] = ffma2(wb.y, h2, pa[3]);
    }
    int node = base + n;
    if (node < N_NODES_C) {
        float o0, o1, o2, o3, o4, o5, o6, o7;
        unpack2(pa[0], o0, o1); unpack2(pa[1], o2, o3);
        unpack2(pa[2], o4, o5); unpack2(pa[3], o6, o7);
        float* dst = (m == 0 ? g_p : g_r) + (size_t)node * OUT_DIM;
        reinterpret_cast<float4*>(dst)[0] = make_float4(o0, o1, o2, o3);
        reinterpret_cast<float4*>(dst)[1] = make_float4(o4, o5, o6, o7);
    }
}

// ---------------- kernel 5: layer-2 gather-mean + finalize (float4) ---------
__global__ void __launch_bounds__(256) k_layerB(const float* __restrict__ b2,
                                                float* __restrict__ out) {
    int tid = threadIdx.x, warp = tid >> 5, lane = tid & 31;
    int jl = lane >> 1, q = lane & 1;
    float4 b4 = *reinterpret_cast<const float4*>(b2 + q * 4);

    int node = blockIdx.x * 8 + warp;
    if (node >= N_NODES_C) return;

    int deg = min(g_cnt[node], MAX_DEG);
    const int* row = g_csr + node * MAX_DEG;
    int s0 = (lane      < deg) ? row[lane]      : 0;
    int s1 = (lane + 32 < deg) ? row[lane + 32] : 0;

    float4 acc = make_float4(0.f, 0.f, 0.f, 0.f);
    int rounds = (deg + 15) >> 4;
    for (int tr = 0; tr < rounds; ++tr) {
        int j = tr * 16 + jl;
        int s = (tr < 2) ? s0 : s1;
        int src = __shfl_sync(0xffffffffu, s, j & 31);
        if (j < deg) {
            float4 v = *reinterpret_cast<const float4*>(g_p + (size_t)src * OUT_DIM + q * 4);
            acc.x += v.x; acc.y += v.y; acc.z += v.z; acc.w += v.w;
        }
    }
#pragma unroll
    for (int off = 2; off <= 16; off <<= 1) {
        acc.x += __shfl_xor_sync(0xffffffffu, acc.x, off);
        acc.y += __shfl_xor_sync(0xffffffffu, acc.y, off);
        acc.z += __shfl_xor_sync(0xffffffffu, acc.z, off);
        acc.w += __shfl_xor_sync(0xffffffffu, acc.w, off);
    }
    if (lane < 2) {
        float inv = 1.0f / fmaxf((float)deg, 1.0f);
        float4 r = *reinterpret_cast<const float4*>(g_r + (size_t)node * OUT_DIM + q * 4);
        float4 o4;
        o4.x = fmaf(acc.x, inv, b4.x) + r.x;
        o4.y = fmaf(acc.y, inv, b4.y) + r.y;
        o4.z = fmaf(acc.z, inv, b4.z) + r.z;
        o4.w = fmaf(acc.w, inv, b4.w) + r.w;
        *reinterpret_cast<float4*>(out + (size_t)node * OUT_DIM + q * 4) = o4;
    }
}

// ---------------- launcher ---------------------------------------------------
extern "C" void kernel_launch(void* const* d_in, const int* in_sizes, int n_in,
                              void* d_out, int out_size) {
    int ix, iei, iW1l, ib1, iW1r, iW2l, ib2, iW2r;
    if (in_sizes[0] > 1000000) {        // dict order (x first)
        ix = 0; iei = 1; iW1l = 2; ib1 = 3; iW1r = 4; iW2l = 5; ib2 = 6; iW2r = 7;
    } else {                            // alphabetical
        iW1l = 0; iW1r = 1; iW2l = 2; iW2r = 3; ib1 = 4; ib2 = 5; iei = 6; ix = 7;
    }
    const float* x   = (const float*)d_in[ix];
    const void*  ei  = d_in[iei];
    const float* W1l = (const float*)d_in[iW1l];
    const float* b1  = (const float*)d_in[ib1];
    const float* W1r = (const float*)d_in[iW1r];
    const float* W2l = (const float*)d_in[iW2l];
    const float* b2  = (const float*)d_in[ib2];
    const float* W2r = (const float*)d_in[iW2r];
    float* out = (float*)d_out;

    static int smem_set = 0;
    if (!smem_set) {
        cudaFuncSetAttribute(k_gemm, cudaFuncAttributeMaxDynamicSharedMemorySize, SMEM_GEMM);
        smem_set = 1;
    }

    k_zero<<<512, 256>>>(ei);
    k_fill<<<(N_EDGES_C + 255) / 256, 256>>>(ei);
    k_agg<<<N_NODES_C / 32, 256>>>(x);
    k_gemm<<<(N_NODES_C + NPB - 1) / NPB, 256, SMEM_GEMM>>>(x, W1l, b1, W1r, W2l, W2r);
    k_layerB<<<(N_NODES_C + 7) / 8, 256>>>(b2, out);
}

// round 8
// speedup vs baseline: 3.6020x; 1.0459x over previous
#include <cuda_runtime.h>
#include <cuda_bf16.h>
#include <stdint.h>

#define N_NODES_C 100000
#define N_EDGES_C 1600000
#define IN_DIM 32
#define HID_DIM 64
#define OUT_DIM 8
#define MAX_DEG 64
#define NPB 128              // nodes per k_gemm block (MMA M)

typedef unsigned long long ull;

// ---------------- scratch (device globals; no allocation allowed) ----------
__device__ int   g_cnt[N_NODES_C];
__device__ int   g_csr[N_NODES_C * MAX_DEG];
__device__ float g_agg[N_NODES_C * IN_DIM];
__device__ float g_p  [N_NODES_C * OUT_DIM];
__device__ float g_r  [N_NODES_C * OUT_DIM];
__device__ int   g_ei_is32;

// ---------------- warp-MMA helpers (sm_80+ PTX, legal on compute_103) --------
__device__ __forceinline__ uint32_t smem_u32(const void* p) {
    uint32_t a;
    asm("{ .reg .u64 t; cvta.to.shared.u64 t, %1; cvt.u32.u64 %0, t; }"
        : "=r"(a) : "l"(p));
    return a;
}
__device__ __forceinline__ void ldsm_x4(uint32_t addr, uint32_t& r0, uint32_t& r1,
                                        uint32_t& r2, uint32_t& r3) {
    asm volatile("ldmatrix.sync.aligned.m8n8.x4.shared.b16 {%0,%1,%2,%3}, [%4];"
                 : "=r"(r0), "=r"(r1), "=r"(r2), "=r"(r3) : "r"(addr) : "memory");
}
__device__ __forceinline__ void mma_bf16(float* c, const uint32_t* a,
                                         uint32_t b0, uint32_t b1) {
    asm volatile("mma.sync.aligned.m16n8k16.row.col.f32.bf16.bf16.f32 "
                 "{%0,%1,%2,%3}, {%4,%5,%6,%7}, {%8,%9}, {%0,%1,%2,%3};"
                 : "+f"(c[0]), "+f"(c[1]), "+f"(c[2]), "+f"(c[3])
                 : "r"(a[0]), "r"(a[1]), "r"(a[2]), "r"(a[3]), "r"(b0), "r"(b1));
}
__device__ __forceinline__ void f2bf_hilo(float v, unsigned short& h, unsigned short& l) {
    __nv_bfloat16 hb = __float2bfloat16_rn(v);
    float r = v - __bfloat162float(hb);
    __nv_bfloat16 lb = __float2bfloat16_rn(r);
    h = __bfloat16_as_ushort(hb);
    l = __bfloat16_as_ushort(lb);
}

// smem layout for k_gemm (dynamic): strides in bf16 elements
#define STRA 136                         // 128 data + 8 pad (272B rows)
#define OFF_A  0                         // A/H: 128 rows -> 34816 B
#define OFF_B  34816                     // B (Wcat): 64 rows -> 17408 B
#define OFF_B2 52224                     // B2 (W2cat): 16 rows -> 4352 B
#define OFF_B1 56576                     // b1: 64 floats = 256 B
#define SMEM_GEMM 56832

// ---------------- kernel 1: zero counters + detect edge dtype ---------------
__global__ void k_zero(const void* __restrict__ ei) {
    const int stride = gridDim.x * blockDim.x;
    int t = blockIdx.x * blockDim.x + threadIdx.x;
    if (t == 0) {
        const long long* p = (const long long*)ei;
        int is32 = 0;
        for (int i = 0; i < 128; ++i) {
            long long v = p[i];
            if (v < 0 || v >= (long long)N_NODES_C) { is32 = 1; break; }
        }
        g_ei_is32 = is32;
    }
    for (int i = t; i < N_NODES_C; i += stride) g_cnt[i] = 0;
}

// ---------------- kernel 2: build padded CSR --------------------------------
__global__ void __launch_bounds__(256) k_fill(const void* __restrict__ ei) {
    int e = blockIdx.x * blockDim.x + threadIdx.x;
    if (e >= N_EDGES_C) return;
    int src, dst;
    if (g_ei_is32) {
        const int* p = (const int*)ei;
        src = p[e];
        dst = p[N_EDGES_C + e];
    } else {
        const long long* p = (const long long*)ei;
        src = (int)p[e];
        dst = (int)p[N_EDGES_C + e];
    }
    int slot = atomicAdd(&g_cnt[dst], 1);
    if (slot < MAX_DEG) g_csr[dst * MAX_DEG + slot] = src;
}

// ---------------- kernel 3: gather-mean, 8 lanes per node -------------------
__global__ void __launch_bounds__(256) k_agg(const float* __restrict__ x) {
    __shared__ int sIdx[32 * MAX_DEG];
    __shared__ int sDeg[32];

    int tid = threadIdx.x;
    int base = blockIdx.x * 32;

    for (int i = tid; i < 32 * MAX_DEG; i += 256) {
        int nl = i >> 6;
        sIdx[i] = g_csr[(base + nl) * MAX_DEG + (i & 63)];
    }
    if (tid < 32) sDeg[tid] = min(g_cnt[base + tid], MAX_DEG);
    __syncthreads();

    int qid = tid >> 3, q = tid & 7;
    int deg = sDeg[qid];
    const int* row = &sIdx[qid * MAX_DEG];

    float4 a0 = make_float4(0.f, 0.f, 0.f, 0.f);
    float4 a1 = a0;
    int j = 0;
    for (; j + 2 <= deg; j += 2) {
        int sa = row[j], sb = row[j + 1];
        float4 va = *reinterpret_cast<const float4*>(x + (size_t)sa * IN_DIM + q * 4);
        float4 vb = *reinterpret_cast<const float4*>(x + (size_t)sb * IN_DIM + q * 4);
        a0.x += va.x; a0.y += va.y; a0.z += va.z; a0.w += va.w;
        a1.x += vb.x; a1.y += vb.y; a1.z += vb.z; a1.w += vb.w;
    }
    if (j < deg) {
        float4 va = *reinterpret_cast<const float4*>(x + (size_t)row[j] * IN_DIM + q * 4);
        a0.x += va.x; a0.y += va.y; a0.z += va.z; a0.w += va.w;
    }
    float inv = 1.0f / fmaxf((float)deg, 1.0f);
    float4 o4;
    o4.x = (a0.x + a1.x) * inv;
    o4.y = (a0.y + a1.y) * inv;
    o4.z = (a0.z + a1.z) * inv;
    o4.w = (a0.w + a1.w) * inv;
    *reinterpret_cast<float4*>(g_agg + (size_t)(base + qid) * IN_DIM + q * 4) = o4;
}

// ---------------- kernel 4: double-MMA fused layer (bf16 hi/lo) -------------
// MMA1: D[128x64] = F[128x64] @ Wcat^T  (12 k-steps: hh + lh + hl)
// epilogue (warp-private): relu(D+b1) -> own A-slab as bf16 hi/lo
// MMA2: [p|r][128x16] = H[128x64] @ W2cat^T (12 k-steps) -> g_p/g_r
__global__ void __launch_bounds__(256, 2) k_gemm(const float* __restrict__ x,
                                                 const float* __restrict__ W1l,
                                                 const float* __restrict__ b1,
                                                 const float* __restrict__ W1r,
                                                 const float* __restrict__ W2l,
                                                 const float* __restrict__ W2r) {
    extern __shared__ unsigned char dynsmem[];
    unsigned short* sA  = reinterpret_cast<unsigned short*>(dynsmem + OFF_A);
    unsigned short* sB  = reinterpret_cast<unsigned short*>(dynsmem + OFF_B);
    unsigned short* sB2 = reinterpret_cast<unsigned short*>(dynsmem + OFF_B2);
    float* sb1 = reinterpret_cast<float*>(dynsmem + OFF_B1);

    const uint32_t sA_u  = smem_u32(sA);
    const uint32_t sB_u  = smem_u32(sB);
    const uint32_t sB2_u = smem_u32(sB2);

    int t = threadIdx.x;
    int wid = t >> 5, lane = t & 31;
    int base = blockIdx.x * NPB;

    // ---- stage A rows: [hi(64) | lo(64)] bf16, feats = (agg | x) ----
    for (int idx = t; idx < NPB * 16; idx += 256) {
        int n = idx >> 4, f4 = idx & 15;
        int node = base + n;
        float4 v = make_float4(0.f, 0.f, 0.f, 0.f);
        if (node < N_NODES_C) {
            v = (f4 < 8)
                ? *reinterpret_cast<const float4*>(g_agg + (size_t)node * IN_DIM + f4 * 4)
                : *reinterpret_cast<const float4*>(x + (size_t)node * IN_DIM + (f4 - 8) * 4);
        }
        float vv[4] = {v.x, v.y, v.z, v.w};
        unsigned short hs[4], ls[4];
#pragma unroll
        for (int k = 0; k < 4; ++k) f2bf_hilo(vv[k], hs[k], ls[k]);
        uint2 hu, lu;
        hu.x = (uint32_t)hs[0] | ((uint32_t)hs[1] << 16);
        hu.y = (uint32_t)hs[2] | ((uint32_t)hs[3] << 16);
        lu.x = (uint32_t)ls[0] | ((uint32_t)ls[1] << 16);
        lu.y = (uint32_t)ls[2] | ((uint32_t)ls[3] << 16);
        *reinterpret_cast<uint2*>(sA + n * STRA + f4 * 4)      = hu;
        *reinterpret_cast<uint2*>(sA + n * STRA + 64 + f4 * 4) = lu;
    }
    // ---- stage B rows (Wcat [o][f]): [hi(64) | lo(64)] ----
    for (int idx = t; idx < 64 * 16; idx += 256) {
        int o = idx >> 4, f4 = idx & 15;
        float4 v = (f4 < 8)
            ? *reinterpret_cast<const float4*>(W1l + o * IN_DIM + f4 * 4)
            : *reinterpret_cast<const float4*>(W1r + o * IN_DIM + (f4 - 8) * 4);
        float vv[4] = {v.x, v.y, v.z, v.w};
        unsigned short hs[4], ls[4];
#pragma unroll
        for (int k = 0; k < 4; ++k) f2bf_hilo(vv[k], hs[k], ls[k]);
        uint2 hu, lu;
        hu.x = (uint32_t)hs[0] | ((uint32_t)hs[1] << 16);
        hu.y = (uint32_t)hs[2] | ((uint32_t)hs[3] << 16);
        lu.x = (uint32_t)ls[0] | ((uint32_t)ls[1] << 16);
        lu.y = (uint32_t)ls[2] | ((uint32_t)ls[3] << 16);
        *reinterpret_cast<uint2*>(sB + o * STRA + f4 * 4)      = hu;
        *reinterpret_cast<uint2*>(sB + o * STRA + 64 + f4 * 4) = lu;
    }
    // ---- stage B2 rows (W2cat [16][64]: rows 0-7 = W2l, 8-15 = W2r) ----
    for (int idx = t; idx < 16 * 16; idx += 256) {
        int o2 = idx >> 4, f4 = idx & 15;
        const float* srcw = (o2 < 8) ? (W2l + o2 * HID_DIM) : (W2r + (o2 - 8) * HID_DIM);
        float4 v = *reinterpret_cast<const float4*>(srcw + f4 * 4);
        float vv[4] = {v.x, v.y, v.z, v.w};
        unsigned short hs[4], ls[4];
#pragma unroll
        for (int k = 0; k < 4; ++k) f2bf_hilo(vv[k], hs[k], ls[k]);
        uint2 hu, lu;
        hu.x = (uint32_t)hs[0] | ((uint32_t)hs[1] << 16);
        hu.y = (uint32_t)hs[2] | ((uint32_t)hs[3] << 16);
        lu.x = (uint32_t)ls[0] | ((uint32_t)ls[1] << 16);
        lu.y = (uint32_t)ls[2] | ((uint32_t)ls[3] << 16);
        *reinterpret_cast<uint2*>(sB2 + o2 * STRA + f4 * 4)      = hu;
        *reinterpret_cast<uint2*>(sB2 + o2 * STRA + 64 + f4 * 4) = lu;
    }
    if (t < HID_DIM) sb1[t] = b1[t];
    __syncthreads();   // the only block-wide sync

    // fragment base addresses (identical addressing for MMA1 and MMA2 A)
    const uint32_t a_base = sA_u + (uint32_t)(((wid * 16 + (lane & 15)) * STRA + (lane >> 4) * 8) * 2);
    const int q = lane >> 3, rr = lane & 7;
    const uint32_t b_base  = sB_u  + (uint32_t)((((q >> 1) * 8 + rr) * STRA + (q & 1) * 8) * 2);
    const uint32_t b2_base = sB2_u + (uint32_t)((((q >> 1) * 8 + rr) * STRA + (q & 1) * 8) * 2);

    const int ka_tab[12] = {0, 1, 2, 3, 4, 5, 6, 7, 0, 1, 2, 3};   // A: hi,lo,hi
    const int kb_tab[12] = {0, 1, 2, 3, 0, 1, 2, 3, 4, 5, 6, 7};   // B: hi,hi,lo

    // ---- MMA1: C[8 ntiles][4] ----
    float c[8][4];
#pragma unroll
    for (int nt = 0; nt < 8; ++nt)
#pragma unroll
        for (int k = 0; k < 4; ++k) c[nt][k] = 0.f;
#pragma unroll
    for (int s = 0; s < 12; ++s) {
        uint32_t a[4];
        ldsm_x4(a_base + (uint32_t)(ka_tab[s] * 32), a[0], a[1], a[2], a[3]);
        uint32_t koff = (uint32_t)(kb_tab[s] * 32);
#pragma unroll
        for (int np = 0; np < 4; ++np) {
            uint32_t b0, b1v, b2v, b3;
            ldsm_x4(b_base + (uint32_t)(np * 16 * STRA * 2) + koff, b0, b1v, b2v, b3);
            mma_bf16(c[2 * np],     a, b0, b1v);
            mma_bf16(c[2 * np + 1], a, b2v, b3);
        }
    }

    // ---- warp-private epilogue: relu(h)+b1 -> own A-slab (bf16 hi/lo) ----
    __syncwarp();
    {
        int g = lane >> 2, cc = lane & 3;
        int m0 = wid * 16 + g;
#pragma unroll
        for (int nt = 0; nt < 8; ++nt) {
            int o0 = nt * 8 + 2 * cc;
            float bi0 = sb1[o0], bi1 = sb1[o0 + 1];
            float v0 = fmaxf(c[nt][0] + bi0, 0.f);
            float v1 = fmaxf(c[nt][1] + bi1, 0.f);
            float v2 = fmaxf(c[nt][2] + bi0, 0.f);
            float v3 = fmaxf(c[nt][3] + bi1, 0.f);
            unsigned short h0, l0, h1, l1, h2, l2, h3, l3;
            f2bf_hilo(v0, h0, l0); f2bf_hilo(v1, h1, l1);
            f2bf_hilo(v2, h2, l2); f2bf_hilo(v3, h3, l3);
            *reinterpret_cast<uint32_t*>(sA + m0 * STRA + o0)            = (uint32_t)h0 | ((uint32_t)h1 << 16);
            *reinterpret_cast<uint32_t*>(sA + m0 * STRA + 64 + o0)       = (uint32_t)l0 | ((uint32_t)l1 << 16);
            *reinterpret_cast<uint32_t*>(sA + (m0 + 8) * STRA + o0)      = (uint32_t)h2 | ((uint32_t)h3 << 16);
            *reinterpret_cast<uint32_t*>(sA + (m0 + 8) * STRA + 64 + o0) = (uint32_t)l2 | ((uint32_t)l3 << 16);
        }
    }
    __syncwarp();

    // ---- MMA2: [p|r][128x16] = H @ W2cat^T ----
    float c2[2][4];
#pragma unroll
    for (int nt = 0; nt < 2; ++nt)
#pragma unroll
        for (int k = 0; k < 4; ++k) c2[nt][k] = 0.f;
#pragma unroll
    for (int s = 0; s < 12; ++s) {
        uint32_t a[4];
        ldsm_x4(a_base + (uint32_t)(ka_tab[s] * 32), a[0], a[1], a[2], a[3]);
        uint32_t b0, b1v, b2v, b3;
        ldsm_x4(b2_base + (uint32_t)(kb_tab[s] * 32), b0, b1v, b2v, b3);
        mma_bf16(c2[0], a, b0, b1v);   // cols 0-7  = p
        mma_bf16(c2[1], a, b2v, b3);   // cols 8-15 = r
    }

    // ---- store p/r from fragments ----
    {
        int g = lane >> 2, cc = lane & 3;
        int m0 = wid * 16 + g;
        int n0 = base + m0, n1 = base + m0 + 8;
        if (n0 < N_NODES_C) {
            *reinterpret_cast<float2*>(g_p + (size_t)n0 * OUT_DIM + 2 * cc) =
                make_float2(c2[0][0], c2[0][1]);
            *reinterpret_cast<float2*>(g_r + (size_t)n0 * OUT_DIM + 2 * cc) =
                make_float2(c2[1][0], c2[1][1]);
        }
        if (n1 < N_NODES_C) {
            *reinterpret_cast<float2*>(g_p + (size_t)n1 * OUT_DIM + 2 * cc) =
                make_float2(c2[0][2], c2[0][3]);
            *reinterpret_cast<float2*>(g_r + (size_t)n1 * OUT_DIM + 2 * cc) =
                make_float2(c2[1][2], c2[1][3]);
        }
    }
}

// ---------------- kernel 5: layer-2 gather-mean + finalize (float4) ---------
__global__ void __launch_bounds__(256) k_layerB(const float* __restrict__ b2,
                                                float* __restrict__ out) {
    int tid = threadIdx.x, warp = tid >> 5, lane = tid & 31;
    int jl = lane >> 1, q = lane & 1;
    float4 b4 = *reinterpret_cast<const float4*>(b2 + q * 4);

    int node = blockIdx.x * 8 + warp;
    if (node >= N_NODES_C) return;

    int deg = min(g_cnt[node], MAX_DEG);
    const int* row = g_csr + node * MAX_DEG;
    int s0 = (lane      < deg) ? row[lane]      : 0;
    int s1 = (lane + 32 < deg) ? row[lane + 32] : 0;

    float4 acc = make_float4(0.f, 0.f, 0.f, 0.f);
    int rounds = (deg + 15) >> 4;
    for (int tr = 0; tr < rounds; ++tr) {
        int j = tr * 16 + jl;
        int s = (tr < 2) ? s0 : s1;
        int src = __shfl_sync(0xffffffffu, s, j & 31);
        if (j < deg) {
            float4 v = *reinterpret_cast<const float4*>(g_p + (size_t)src * OUT_DIM + q * 4);
            acc.x += v.x; acc.y += v.y; acc.z += v.z; acc.w += v.w;
        }
    }
#pragma unroll
    for (int off = 2; off <= 16; off <<= 1) {
        acc.x += __shfl_xor_sync(0xffffffffu, acc.x, off);
        acc.y += __shfl_xor_sync(0xffffffffu, acc.y, off);
        acc.z += __shfl_xor_sync(0xffffffffu, acc.z, off);
        acc.w += __shfl_xor_sync(0xffffffffu, acc.w, off);
    }
    if (lane < 2) {
        float inv = 1.0f / fmaxf((float)deg, 1.0f);
        float4 r = *reinterpret_cast<const float4*>(g_r + (size_t)node * OUT_DIM + q * 4);
        float4 o4;
        o4.x = fmaf(acc.x, inv, b4.x) + r.x;
        o4.y = fmaf(acc.y, inv, b4.y) + r.y;
        o4.z = fmaf(acc.z, inv, b4.z) + r.z;
        o4.w = fmaf(acc.w, inv, b4.w) + r.w;
        *reinterpret_cast<float4*>(out + (size_t)node * OUT_DIM + q * 4) = o4;
    }
}

// ---------------- launcher ---------------------------------------------------
extern "C" void kernel_launch(void* const* d_in, const int* in_sizes, int n_in,
                              void* d_out, int out_size) {
    int ix, iei, iW1l, ib1, iW1r, iW2l, ib2, iW2r;
    if (in_sizes[0] > 1000000) {        // dict order (x first)
        ix = 0; iei = 1; iW1l = 2; ib1 = 3; iW1r = 4; iW2l = 5; ib2 = 6; iW2r = 7;
    } else {                            // alphabetical
        iW1l = 0; iW1r = 1; iW2l = 2; iW2r = 3; ib1 = 4; ib2 = 5; iei = 6; ix = 7;
    }
    const float* x   = (const float*)d_in[ix];
    const void*  ei  = d_in[iei];
    const float* W1l = (const float*)d_in[iW1l];
    const float* b1  = (const float*)d_in[ib1];
    const float* W1r = (const float*)d_in[iW1r];
    const float* W2l = (const float*)d_in[iW2l];
    const float* b2  = (const float*)d_in[ib2];
    const float* W2r = (const float*)d_in[iW2r];
    float* out = (float*)d_out;

    static int smem_set = 0;
    if (!smem_set) {
        cudaFuncSetAttribute(k_gemm, cudaFuncAttributeMaxDynamicSharedMemorySize, SMEM_GEMM);
        cudaFuncSetAttribute(k_gemm, cudaFuncAttributePreferredSharedMemoryCarveout, 100);
        smem_set = 1;
    }

    k_zero<<<512, 256>>>(ei);
    k_fill<<<(N_EDGES_C + 255) / 256, 256>>>(ei);
    k_agg<<<N_NODES_C / 32, 256>>>(x);
    k_gemm<<<(N_NODES_C + NPB - 1) / NPB, 256, SMEM_GEMM>>>(x, W1l, b1, W1r, W2l, W2r);
    k_layerB<<<(N_NODES_C + 7) / 8, 256>>>(b2, out);
}